// round 1
// baseline (speedup 1.0000x reference)
#include <cuda_runtime.h>
#include <math.h>

#define BB 8
#define PP 4096
#define CC 91
#define CM1 90
#define SPI (PP*CM1)          // 368640 scores per image
#define FD 1024
#define DETS 100
#define H1 1024
#define H2 4096
#define CAND_CAP 2048
#define BBOX_CLIP 4.135166556742356f
#define IMGF 800.0f

__device__ __align__(16) unsigned int g_scores[BB*SPI];
__device__ int g_hist1[BB*H1];
__device__ int g_hist2[BB*H2];
__device__ int g_cb[BB];
__device__ int g_above1[BB];
__device__ unsigned int g_T24[BB];
__device__ unsigned long long g_cand[BB*CAND_CAP];
__device__ int g_ccount[BB];
__device__ int g_keptp[BB*DETS];

__global__ void init_k() {
    int i = blockIdx.x * blockDim.x + threadIdx.x;
    if (i < BB*H1) g_hist1[i] = 0;
    if (i < BB*H2) g_hist2[i] = 0;
    if (i < BB)    g_ccount[i] = 0;
}

// One warp per proposal row: softmax over 91 logits, emit score bit patterns
// for classes 1..90, accumulate coarse histogram (float bits >> 20, < 1024 bins
// since scores are in (0,1]).
__global__ void softmax_hist_k(const float* __restrict__ logits) {
    __shared__ int sh[H1];
    int tid = threadIdx.x;
    for (int i = tid; i < H1; i += 256) sh[i] = 0;
    __syncthreads();

    int warp = tid >> 5, lane = tid & 31;
    int row = blockIdx.x * 8 + warp;          // 4096 blocks x 8 warps = 32768 rows
    int img = row >> 12;                      // 4096 rows per image
    int p = row & (PP - 1);
    const float* l = logits + (size_t)row * CC;

    float v0 = l[lane];                       // c = lane      (0..31)
    float v1 = l[lane + 32];                  // c = lane+32   (32..63)
    float v2 = (lane + 64 < CC) ? l[lane + 64] : -1e30f;  // c = lane+64 (64..90)

    float m = fmaxf(v0, fmaxf(v1, v2));
    #pragma unroll
    for (int o = 16; o; o >>= 1) m = fmaxf(m, __shfl_xor_sync(0xffffffffu, m, o));

    float e0 = expf(v0 - m);
    float e1 = expf(v1 - m);
    float e2 = (lane + 64 < CC) ? expf(v2 - m) : 0.0f;
    float s = e0 + e1 + e2;
    #pragma unroll
    for (int o = 16; o; o >>= 1) s += __shfl_xor_sync(0xffffffffu, s, o);

    unsigned base = (unsigned)img * SPI + (unsigned)p * CM1;
    if (lane > 0) {  // skip background class 0
        unsigned b = __float_as_uint(e0 / s);
        g_scores[base + lane - 1] = b;
        atomicAdd(&sh[b >> 20], 1);
    }
    {
        unsigned b = __float_as_uint(e1 / s);
        g_scores[base + lane + 31] = b;
        atomicAdd(&sh[b >> 20], 1);
    }
    if (lane + 64 < CC) {
        unsigned b = __float_as_uint(e2 / s);
        g_scores[base + lane + 63] = b;
        atomicAdd(&sh[b >> 20], 1);
    }
    __syncthreads();
    int bimg = blockIdx.x >> 9;               // all warps in block share one image
    for (int i = tid; i < H1; i += 256) {
        int v = sh[i];
        if (v) atomicAdd(&g_hist1[bimg * H1 + i], v);
    }
}

__global__ void thresh1_k() {
    int img = blockIdx.x;
    __shared__ int sh[H1];
    for (int i = threadIdx.x; i < H1; i += blockDim.x) sh[i] = g_hist1[img * H1 + i];
    __syncthreads();
    if (threadIdx.x == 0) {
        int cum = 0;
        for (int b = H1 - 1; b >= 0; b--) {
            int h = sh[b];
            if (cum + h >= DETS) { g_cb[img] = b; g_above1[img] = cum; break; }
            cum += h;
        }
    }
}

__global__ void hist2_k() {
    int t = blockIdx.x * blockDim.x + threadIdx.x;   // over total/4
    const uint4* sp = (const uint4*)g_scores;
    uint4 v = sp[t];
    int base = t * 4;
    int img = base / SPI;
    unsigned cb = (unsigned)g_cb[img];
    unsigned a[4] = {v.x, v.y, v.z, v.w};
    #pragma unroll
    for (int j = 0; j < 4; j++)
        if ((a[j] >> 20) == cb)
            atomicAdd(&g_hist2[img * H2 + ((a[j] >> 8) & 0xFFF)], 1);
}

__global__ void thresh2_k() {
    int img = blockIdx.x;
    __shared__ int sh[H2];
    for (int i = threadIdx.x; i < H2; i += blockDim.x) sh[i] = g_hist2[img * H2 + i];
    __syncthreads();
    if (threadIdx.x == 0) {
        int need = DETS - g_above1[img];
        int cum = 0, fb = 0;
        for (int b = H2 - 1; b >= 0; b--) {
            int h = sh[b];
            if (cum + h >= need) { fb = b; break; }
            cum += h;
        }
        g_T24[img] = (((unsigned)g_cb[img]) << 12) | (unsigned)fb;
    }
}

__global__ void compact_k() {
    int t = blockIdx.x * blockDim.x + threadIdx.x;
    const uint4* sp = (const uint4*)g_scores;
    uint4 v = sp[t];
    int base = t * 4;
    int img = base / SPI;
    unsigned T = g_T24[img];
    unsigned local = (unsigned)(base - img * SPI);
    unsigned a[4] = {v.x, v.y, v.z, v.w};
    #pragma unroll
    for (int j = 0; j < 4; j++) {
        if ((a[j] >> 8) >= T) {
            int pos = atomicAdd(&g_ccount[img], 1);
            if (pos < CAND_CAP)
                g_cand[img * CAND_CAP + pos] =
                    (((unsigned long long)a[j]) << 32) | (unsigned)(~(local + j));
        }
    }
}

// One block per image: bitonic-sort candidates descending by 64-bit key
// (score bits, then smaller index first), take top-100, decode boxes.
__global__ void final_k(const float* __restrict__ reg,
                        const float* __restrict__ props,
                        float* __restrict__ out) {
    int img = blockIdx.x;
    __shared__ unsigned long long sk[CAND_CAP];
    int n = g_ccount[img];
    if (n > CAND_CAP) n = CAND_CAP;
    for (int i = threadIdx.x; i < CAND_CAP; i += blockDim.x)
        sk[i] = (i < n) ? g_cand[img * CAND_CAP + i] : 0ull;
    __syncthreads();

    for (int k = 2; k <= CAND_CAP; k <<= 1) {
        for (int j = k >> 1; j > 0; j >>= 1) {
            for (int i = threadIdx.x; i < CAND_CAP; i += blockDim.x) {
                int ixj = i ^ j;
                if (ixj > i) {
                    bool up = ((i & k) == 0);
                    unsigned long long a = sk[i], b = sk[ixj];
                    if ((a < b) == up) { sk[i] = b; sk[ixj] = a; }  // descending
                }
            }
            __syncthreads();
        }
    }

    if (threadIdx.x < DETS) {
        int d = threadIdx.x;
        unsigned long long key = sk[d];
        unsigned idxl = ~(unsigned)(key & 0xFFFFFFFFull);
        int p = idxl / CM1;
        int c = idxl - p * CM1 + 1;

        const float* pr = props + ((size_t)img * PP + p) * 4;
        float x1 = pr[0], y1 = pr[1], x2 = pr[2], y2 = pr[3];
        float w = x2 - x1, h = y2 - y1;
        float cx = x1 + 0.5f * w, cy = y1 + 0.5f * h;

        const float* rg = reg + ((size_t)img * PP + p) * (4 * CC) + 4 * c;
        float dx = rg[0] / 10.0f;
        float dy = rg[1] / 10.0f;
        float dw = fminf(rg[2] / 5.0f, BBOX_CLIP);
        float dh = fminf(rg[3] / 5.0f, BBOX_CLIP);

        float pcx = dx * w + cx, pcy = dy * h + cy;
        float pw = expf(dw) * w, ph = expf(dh) * h;

        float bx1 = pcx - 0.5f * pw, by1 = pcy - 0.5f * ph;
        float bx2 = pcx + 0.5f * pw, by2 = pcy + 0.5f * ph;
        bx1 = fminf(fmaxf(bx1, 0.0f), IMGF);
        bx2 = fminf(fmaxf(bx2, 0.0f), IMGF);
        by1 = fminf(fmaxf(by1, 0.0f), IMGF);
        by2 = fminf(fmaxf(by2, 0.0f), IMGF);

        float* ob = out + ((size_t)img * DETS + d) * 4;
        ob[0] = bx1 / IMGF;
        ob[1] = by1 / IMGF;
        ob[2] = bx2 / IMGF;
        ob[3] = by2 / IMGF;
        g_keptp[img * DETS + d] = p;
    }
}

__global__ void gather_k(const float* __restrict__ feats, float* __restrict__ out) {
    int img = blockIdx.x / DETS;
    int p = g_keptp[blockIdx.x];
    const float4* src = (const float4*)(feats + ((size_t)img * PP + p) * FD);
    float4* dst = (float4*)(out + BB * DETS * 4 + (size_t)blockIdx.x * FD);
    dst[threadIdx.x] = src[threadIdx.x];   // 256 threads x float4 = 1024 floats
}

extern "C" void kernel_launch(void* const* d_in, const int* in_sizes, int n_in,
                              void* d_out, int out_size) {
    const float* logits = (const float*)d_in[0];
    const float* reg    = (const float*)d_in[1];
    const float* props  = (const float*)d_in[2];
    const float* feats  = (const float*)d_in[3];
    float* out = (float*)d_out;

    init_k<<<(BB * H2 + 255) / 256, 256>>>();
    softmax_hist_k<<<BB * PP / 8, 256>>>(logits);
    thresh1_k<<<BB, 256>>>();
    hist2_k<<<BB * SPI / 4 / 256, 256>>>();
    thresh2_k<<<BB, 256>>>();
    compact_k<<<BB * SPI / 4 / 256, 256>>>();
    final_k<<<BB, 256>>>(reg, props, out);
    gather_k<<<BB * DETS, 256>>>(feats, out);
}

// round 2
// speedup vs baseline: 3.7929x; 3.7929x over previous
#include <cuda_runtime.h>
#include <math.h>

#define BB 8
#define PP 4096
#define CC 91
#define CM1 90
#define FD 1024
#define DETS 100
#define ROWCAP 512
#define CANDCAP 1024
#define BBOX_CLIP 4.135166556742356f
#define IMGF 800.0f

__device__ unsigned int g_rowmax[BB * PP];
__device__ int g_keptp[BB * DETS];

// ---------------------------------------------------------------------------
// K1: warp per proposal row. Softmax over 91 logits; store only the max score
// over classes 1..90 (background excluded from ranking, included in denom)
// as its float bit pattern (positive floats order as uints).
// ---------------------------------------------------------------------------
__global__ void rowmax_k(const float* __restrict__ logits) {
    int tid = threadIdx.x;
    int warp = tid >> 5, lane = tid & 31;
    int row = blockIdx.x * 8 + warp;               // 4096 blocks x 8 warps
    const float* l = logits + (size_t)row * CC;

    float v0 = l[lane];
    float v1 = l[lane + 32];
    float v2 = (lane < 27) ? l[lane + 64] : -1e30f;

    float m = fmaxf(v0, fmaxf(v1, v2));
    #pragma unroll
    for (int o = 16; o; o >>= 1) m = fmaxf(m, __shfl_xor_sync(0xffffffffu, m, o));

    float e0 = expf(v0 - m);
    float e1 = expf(v1 - m);
    float e2 = (lane < 27) ? expf(v2 - m) : 0.0f;
    float s = e0 + e1 + e2;
    #pragma unroll
    for (int o = 16; o; o >>= 1) s += __shfl_xor_sync(0xffffffffu, s, o);

    float best = fmaxf((lane > 0) ? e0 : 0.0f, fmaxf(e1, e2));
    #pragma unroll
    for (int o = 16; o; o >>= 1) best = fmaxf(best, __shfl_xor_sync(0xffffffffu, best, o));

    if (lane == 0) g_rowmax[row] = __float_as_uint(best / s);
}

// ---------------------------------------------------------------------------
// K2: one block (512 threads) per image. Radix-select threshold on rowmaxes,
// compact candidate rows, re-softmax those rows, exact stable top-100 via
// bitonic sort on (score_bits << 32) | ~local_index, decode + clip boxes.
// ---------------------------------------------------------------------------
__global__ void __launch_bounds__(512, 1) select_k(const float* __restrict__ logits,
                                                   const float* __restrict__ reg,
                                                   const float* __restrict__ props,
                                                   float* __restrict__ out) {
    __shared__ unsigned vals[PP];                    // 16 KB
    __shared__ int h[256];
    __shared__ int rowbuf[ROWCAP];
    __shared__ unsigned long long cand[CANDCAP];     // 8 KB
    __shared__ int s_nrows, s_ncand, s_b1, s_cumAbove;
    __shared__ unsigned s_T;

    int img = blockIdx.x;
    int tid = threadIdx.x;

    // Phase A: load rowmaxes, coarse 256-bin hist (bits >> 22; max 0x3F8>>2=254)
    for (int i = tid; i < PP; i += 512) vals[i] = g_rowmax[img * PP + i];
    if (tid < 256) h[tid] = 0;
    if (tid == 0) { s_nrows = 0; s_ncand = 0; }
    __syncthreads();
    for (int i = tid; i < PP; i += 512) atomicAdd(&h[vals[i] >> 22], 1);
    __syncthreads();
    if (tid == 0) {
        int cum = 0;
        for (int b = 255; b >= 0; b--) {
            int c = h[b];
            if (cum + c >= DETS) { s_b1 = b; s_cumAbove = cum; break; }
            cum += c;
        }
    }
    __syncthreads();
    int b1 = s_b1;

    // Phase B: fine 256-bin hist within the coarse bin (next 8 bits)
    if (tid < 256) h[tid] = 0;
    __syncthreads();
    for (int i = tid; i < PP; i += 512) {
        unsigned v = vals[i];
        if ((int)(v >> 22) == b1) atomicAdd(&h[(v >> 14) & 0xFF], 1);
    }
    __syncthreads();
    if (tid == 0) {
        int need = DETS - s_cumAbove;
        int cum = 0, fb = 0;
        for (int b = 255; b >= 0; b--) {
            int c = h[b];
            if (cum + c >= need) { fb = b; break; }
            cum += c;
        }
        s_T = ((unsigned)b1 << 8) | (unsigned)fb;    // 16-bit threshold on bits>>14
    }
    __syncthreads();
    unsigned T = s_T;

    // Phase C: compact candidate rows (rowmax >= T)
    for (int i = tid; i < PP; i += 512) {
        if ((vals[i] >> 14) >= T) {
            int pos = atomicAdd(&s_nrows, 1);
            if (pos < ROWCAP) rowbuf[pos] = i;
        }
    }
    for (int i = tid; i < CANDCAP; i += 512) cand[i] = 0ull;
    __syncthreads();
    int nrows = min(s_nrows, ROWCAP);

    // Phase D: re-softmax candidate rows (warp per row), emit keys for scores >= T
    int warp = tid >> 5, lane = tid & 31;
    for (int r = warp; r < nrows; r += 16) {
        int p = rowbuf[r];
        const float* l = logits + (size_t)(img * PP + p) * CC;
        float v0 = l[lane];
        float v1 = l[lane + 32];
        float v2 = (lane < 27) ? l[lane + 64] : -1e30f;
        float m = fmaxf(v0, fmaxf(v1, v2));
        #pragma unroll
        for (int o = 16; o; o >>= 1) m = fmaxf(m, __shfl_xor_sync(0xffffffffu, m, o));
        float e0 = expf(v0 - m);
        float e1 = expf(v1 - m);
        float e2 = (lane < 27) ? expf(v2 - m) : 0.0f;
        float s = e0 + e1 + e2;
        #pragma unroll
        for (int o = 16; o; o >>= 1) s += __shfl_xor_sync(0xffffffffu, s, o);

        unsigned base = (unsigned)p * CM1;
        if (lane > 0) {
            unsigned b = __float_as_uint(e0 / s);
            if ((b >> 14) >= T) {
                int pos = atomicAdd(&s_ncand, 1);
                if (pos < CANDCAP)
                    cand[pos] = (((unsigned long long)b) << 32) | (unsigned)(~(base + lane - 1));
            }
        }
        {
            unsigned b = __float_as_uint(e1 / s);
            if ((b >> 14) >= T) {
                int pos = atomicAdd(&s_ncand, 1);
                if (pos < CANDCAP)
                    cand[pos] = (((unsigned long long)b) << 32) | (unsigned)(~(base + lane + 31));
            }
        }
        if (lane < 27) {
            unsigned b = __float_as_uint(e2 / s);
            if ((b >> 14) >= T) {
                int pos = atomicAdd(&s_ncand, 1);
                if (pos < CANDCAP)
                    cand[pos] = (((unsigned long long)b) << 32) | (unsigned)(~(base + lane + 63));
            }
        }
    }
    __syncthreads();

    // Phase E: bitonic sort 1024 keys descending (padding 0 sinks to bottom)
    for (int k = 2; k <= CANDCAP; k <<= 1) {
        for (int j = k >> 1; j > 0; j >>= 1) {
            for (int i = tid; i < CANDCAP; i += 512) {
                int ixj = i ^ j;
                if (ixj > i) {
                    bool up = ((i & k) == 0);
                    unsigned long long a = cand[i], b = cand[ixj];
                    if ((a < b) == up) { cand[i] = b; cand[ixj] = a; }
                }
            }
            __syncthreads();
        }
    }

    // Phase F: decode top-100 boxes (torchvision BoxCoder), clip, scale
    if (tid < DETS) {
        int d = tid;
        unsigned long long key = cand[d];
        unsigned idxl = ~(unsigned)(key & 0xFFFFFFFFull);
        int p = idxl / CM1;
        int c = idxl - p * CM1 + 1;

        const float* pr = props + ((size_t)img * PP + p) * 4;
        float x1 = pr[0], y1 = pr[1], x2 = pr[2], y2 = pr[3];
        float w = x2 - x1, hh = y2 - y1;
        float cx = x1 + 0.5f * w, cy = y1 + 0.5f * hh;

        const float* rg = reg + ((size_t)img * PP + p) * (4 * CC) + 4 * c;
        float dx = rg[0] / 10.0f;
        float dy = rg[1] / 10.0f;
        float dw = fminf(rg[2] / 5.0f, BBOX_CLIP);
        float dh = fminf(rg[3] / 5.0f, BBOX_CLIP);

        float pcx = dx * w + cx, pcy = dy * hh + cy;
        float pw = expf(dw) * w, ph = expf(dh) * hh;

        float bx1 = fminf(fmaxf(pcx - 0.5f * pw, 0.0f), IMGF);
        float by1 = fminf(fmaxf(pcy - 0.5f * ph, 0.0f), IMGF);
        float bx2 = fminf(fmaxf(pcx + 0.5f * pw, 0.0f), IMGF);
        float by2 = fminf(fmaxf(pcy + 0.5f * ph, 0.0f), IMGF);

        float* ob = out + ((size_t)img * DETS + d) * 4;
        ob[0] = bx1 / IMGF;
        ob[1] = by1 / IMGF;
        ob[2] = bx2 / IMGF;
        ob[3] = by2 / IMGF;
        g_keptp[img * DETS + d] = p;
    }
}

// ---------------------------------------------------------------------------
// K3: feature gather, one block per detection, float4 vectorized
// ---------------------------------------------------------------------------
__global__ void gather_k(const float* __restrict__ feats, float* __restrict__ out) {
    int img = blockIdx.x / DETS;
    int p = g_keptp[blockIdx.x];
    const float4* src = (const float4*)(feats + ((size_t)img * PP + p) * FD);
    float4* dst = (float4*)(out + BB * DETS * 4 + (size_t)blockIdx.x * FD);
    dst[threadIdx.x] = src[threadIdx.x];   // 256 threads x float4 = 1024 floats
}

extern "C" void kernel_launch(void* const* d_in, const int* in_sizes, int n_in,
                              void* d_out, int out_size) {
    const float* logits = (const float*)d_in[0];
    const float* reg    = (const float*)d_in[1];
    const float* props  = (const float*)d_in[2];
    const float* feats  = (const float*)d_in[3];
    float* out = (float*)d_out;

    rowmax_k<<<BB * PP / 8, 256>>>(logits);
    select_k<<<BB, 512>>>(logits, reg, props, out);
    gather_k<<<BB * DETS, 256>>>(feats, out);
}

// round 3
// speedup vs baseline: 6.7145x; 1.7703x over previous
#include <cuda_runtime.h>
#include <math.h>

#define BB 8
#define PP 4096
#define CC 91
#define CM1 90
#define FD 1024
#define DETS 100
#define ROWCAP 512
#define CANDCAP 1024
#define BBOX_CLIP 4.135166556742356f
#define IMGF 800.0f
#define RT 128

__device__ unsigned int g_rowmax[BB * PP];
__device__ int g_keptp[BB * DETS];

__global__ void __launch_bounds__(RT) rowmax_k(const float* __restrict__ logits) {
    __shared__ float s[RT * CC];               // 46592 bytes
    int tid = threadIdx.x;
    const float4* src = (const float4*)(logits + (size_t)blockIdx.x * RT * CC);
    float4* dst = (float4*)s;
    #pragma unroll
    for (int i = tid; i < RT * CC / 4; i += RT) dst[i] = src[i];
    __syncthreads();

    const float* r = s + tid * CC;
    float v0 = r[0];
    float a0 = r[1], a1 = r[2], a2 = r[3], a3 = r[4];
    #pragma unroll
    for (int j = 5; j + 3 < 91; j += 4) {
        a0 = fmaxf(a0, r[j]); a1 = fmaxf(a1, r[j+1]);
        a2 = fmaxf(a2, r[j+2]); a3 = fmaxf(a3, r[j+3]);
    }
    a0 = fmaxf(a0, r[89]); a1 = fmaxf(a1, r[90]);
    float m1 = fmaxf(fmaxf(a0, a1), fmaxf(a2, a3));
    float m = fmaxf(v0, m1);

    float s0 = __expf(v0 - m), s1 = 0.f, s2 = 0.f, s3 = 0.f;
    #pragma unroll
    for (int j = 1; j + 3 < 91; j += 4) {
        s0 += __expf(r[j]   - m); s1 += __expf(r[j+1] - m);
        s2 += __expf(r[j+2] - m); s3 += __expf(r[j+3] - m);
    }
    s0 += __expf(r[89] - m); s1 += __expf(r[90] - m);
    float sum = (s0 + s1) + (s2 + s3);
    float score = __expf(m1 - m) / sum;
    g_rowmax[blockIdx.x * RT + tid] = __float_as_uint(score);
}

__device__ __forceinline__ void find_thresh(const int* h, int need, int* s_b, int* s_cum) {
    int L = threadIdx.x;              // tid < 32 only
    int hi = 255 - 8 * L;
    int hb[8], cs = 0;
    #pragma unroll
    for (int j = 0; j < 8; j++) { hb[j] = h[hi - j]; cs += hb[j]; }
    int pref = cs;
    #pragma unroll
    for (int o = 1; o < 32; o <<= 1) {
        int t = __shfl_up_sync(0xffffffffu, pref, o);
        if (L >= o) pref += t;
    }
    int above = pref - cs;
    if (above < need && need <= pref) {
        int cum = above;
        #pragma unroll
        for (int j = 0; j < 8; j++) {
            if (cum + hb[j] >= need) { *s_b = hi - j; *s_cum = cum; break; }
            cum += hb[j];
        }
    }
}

__global__ void __launch_bounds__(1024, 1) select_k(const float* __restrict__ logits,
                                                    const float* __restrict__ reg,
                                                    const float* __restrict__ props,
                                                    float* __restrict__ out) {
    __shared__ unsigned vals[PP];
    __shared__ int h[256];
    __shared__ int rowbuf[ROWCAP];
    __shared__ unsigned long long cand[CANDCAP];
    __shared__ int s_nrows, s_ncand, s_b1, s_cumAbove, s_fb, s_fcum;

    int img = blockIdx.x;
    int tid = threadIdx.x;
    int lane = tid & 31;

    #pragma unroll
    for (int i = tid; i < PP; i += 1024) vals[i] = g_rowmax[img * PP + i];
    if (tid < 256) h[tid] = 0;
    if (tid == 0) { s_nrows = 0; s_ncand = 0; }
    __syncthreads();
    #pragma unroll
    for (int i = tid; i < PP; i += 1024) {
        int bin = vals[i] >> 22;
        unsigned peers = __match_any_sync(0xffffffffu, bin);
        if (lane == __ffs(peers) - 1) atomicAdd(&h[bin], __popc(peers));
    }
    __syncthreads();
    if (tid < 32) find_thresh(h, DETS, &s_b1, &s_cumAbove);
    __syncthreads();
    int b1 = s_b1;

    if (tid < 256) h[tid] = 0;
    __syncthreads();
    #pragma unroll
    for (int i = tid; i < PP; i += 1024) {
        unsigned v = vals[i];
        bool pred = ((int)(v >> 22) == b1);
        unsigned active = __ballot_sync(0xffffffffu, pred);
        if (pred) {
            int bin = (v >> 14) & 0xFF;
            unsigned peers = __match_any_sync(active, bin);
            if (lane == __ffs(peers) - 1) atomicAdd(&h[bin], __popc(peers));
        }
    }
    __syncthreads();
    if (tid < 32) find_thresh(h, DETS - s_cumAbove, &s_fb, &s_fcum);
    __syncthreads();
    unsigned T = ((unsigned)b1 << 8) | (unsigned)s_fb;
    unsigned Tc = (T >= 2) ? T - 2 : 0;
    unsigned Te = (T >= 1) ? T - 1 : 0;

    for (int i = tid; i < PP; i += 1024) {
        bool keep = (vals[i] >> 14) >= Tc;
        unsigned b = __ballot_sync(0xffffffffu, keep);
        int cnt = __popc(b);
        if (cnt) {
            int basepos = 0;
            if (lane == 0) basepos = atomicAdd(&s_nrows, cnt);
            basepos = __shfl_sync(0xffffffffu, basepos, 0);
            if (keep) {
                int pos = basepos + __popc(b & ((1u << lane) - 1));
                if (pos < ROWCAP) rowbuf[pos] = i;
            }
        }
    }
    __syncthreads();
    int nrows = min(s_nrows, ROWCAP);

    int warp = tid >> 5;
    for (int r = warp; r < nrows; r += 32) {
        int p = rowbuf[r];
        const float* l = logits + (size_t)(img * PP + p) * CC;
        float v0 = l[lane];
        float v1 = l[lane + 32];
        float v2 = (lane < 27) ? l[lane + 64] : -1e30f;
        float m = fmaxf(v0, fmaxf(v1, v2));
        #pragma unroll
        for (int o = 16; o; o >>= 1) m = fmaxf(m, __shfl_xor_sync(0xffffffffu, m, o));
        float e0 = expf(v0 - m);
        float e1 = expf(v1 - m);
        float e2 = (lane < 27) ? expf(v2 - m) : 0.0f;
        float s = e0 + e1 + e2;
        #pragma unroll
        for (int o = 16; o; o >>= 1) s += __shfl_xor_sync(0xffffffffu, s, o);

        unsigned base = (unsigned)p * CM1;
        if (lane > 0) {
            unsigned b = __float_as_uint(e0 / s);
            if ((b >> 14) >= Te) {
                int pos = atomicAdd(&s_ncand, 1);
                if (pos < CANDCAP)
                    cand[pos] = (((unsigned long long)b) << 32) | (unsigned)(~(base + lane - 1));
            }
        }
        {
            unsigned b = __float_as_uint(e1 / s);
            if ((b >> 14) >= Te) {
                int pos = atomicAdd(&s_ncand, 1);
                if (pos < CANDCAP)
                    cand[pos] = (((unsigned long long)b) << 32) | (unsigned)(~(base + lane + 31));
            }
        }
        if (lane < 27) {
            unsigned b = __float_as_uint(e2 / s);
            if ((b >> 14) >= Te) {
                int pos = atomicAdd(&s_ncand, 1);
                if (pos < CANDCAP)
                    cand[pos] = (((unsigned long long)b) << 32) | (unsigned)(~(base + lane + 63));
            }
        }
    }
    __syncthreads();

    int nc = min(s_ncand, CANDCAP);
    if (tid < nc) {
        unsigned long long my = cand[tid];
        int rank = 0;
        for (int j = 0; j < nc; j++) rank += (cand[j] > my);
        if (rank < DETS) {
            unsigned idxl = ~(unsigned)(my & 0xFFFFFFFFull);
            int p = idxl / CM1;
            int c = idxl - p * CM1 + 1;

            const float* pr = props + ((size_t)img * PP + p) * 4;
            float x1 = pr[0], y1 = pr[1], x2 = pr[2], y2 = pr[3];
            float w = x2 - x1, hh = y2 - y1;
            float cx = x1 + 0.5f * w, cy = y1 + 0.5f * hh;

            const float* rg = reg + ((size_t)img * PP + p) * (4 * CC) + 4 * c;
            float dx = rg[0] / 10.0f;
            float dy = rg[1] / 10.0f;
            float dw = fminf(rg[2] / 5.0f, BBOX_CLIP);
            float dh = fminf(rg[3] / 5.0f, BBOX_CLIP);

            float pcx = dx * w + cx, pcy = dy * hh + cy;
            float pw = expf(dw) * w, ph = expf(dh) * hh;

            float bx1 = fminf(fmaxf(pcx - 0.5f * pw, 0.0f), IMGF);
            float by1 = fminf(fmaxf(pcy - 0.5f * ph, 0.0f), IMGF);
            float bx2 = fminf(fmaxf(pcx + 0.5f * pw, 0.0f), IMGF);
            float by2 = fminf(fmaxf(pcy + 0.5f * ph, 0.0f), IMGF);

            float* ob = out + ((size_t)img * DETS + rank) * 4;
            ob[0] = bx1 / IMGF;
            ob[1] = by1 / IMGF;
            ob[2] = bx2 / IMGF;
            ob[3] = by2 / IMGF;
            g_keptp[img * DETS + rank] = p;
        }
    }
}

__global__ void gather_k(const float* __restrict__ feats, float* __restrict__ out) {
    int img = blockIdx.x / DETS;
    int p = g_keptp[blockIdx.x];
    const float4* src = (const float4*)(feats + ((size_t)img * PP + p) * FD);
    float4* dst = (float4*)(out + BB * DETS * 4 + (size_t)blockIdx.x * FD);
    dst[threadIdx.x] = src[threadIdx.x];
}

extern "C" void kernel_launch(void* const* d_in, const int* in_sizes, int n_in,
                              void* d_out, int out_size) {
    const float* logits = (const float*)d_in[0];
    const float* reg    = (const float*)d_in[1];
    const float* props  = (const float*)d_in[2];
    const float* feats  = (const float*)d_in[3];
    float* out = (float*)d_out;

    rowmax_k<<<BB * PP / RT, RT>>>(logits);
    select_k<<<BB, 1024>>>(logits, reg, props, out);
    gather_k<<<BB * DETS, 256>>>(feats, out);
}